// round 2
// baseline (speedup 1.0000x reference)
#include <cuda_runtime.h>

// Problem constants (fixed shapes)
#define BDIM 32
#define NDIM 2048
#define HDIM 512
#define MASK_NEG 1e30f

// V-stream kernel geometry: one block per (b, 32-float h-slab)
#define SLABS   16            // HDIM / 32
#define GROUPS  64            // n-groups per block
#define RPG     32            // rows per group (GROUPS*RPG = NDIM)

// Scratch (device globals: allowed; no runtime allocation)
__device__ float g_alpha[BDIM * NDIM];   // masked attention logits
__device__ float g_y0T[HDIM * BDIM];     // y0 transposed [h][b]
__device__ float g_y1T[HDIM * BDIM];     // y1 transposed [h][b]
__device__ float g_qT [HDIM * BDIM];     // Q  transposed [h][b]

// ---------------------------------------------------------------------------
// K1: alpha[b,n] = K[b,n,:] . wk - (1-adj)*1e30
// (Q.wq + b_att are per-row constants -> cancel in softmax, skipped.)
// 2 rows per warp, 8 LDG.128 per lane issued back-to-back (MLP=8).
// ---------------------------------------------------------------------------
__global__ __launch_bounds__(256)
void k_alpha(const float* __restrict__ Kmat,
             const float* __restrict__ w_att,
             const int*   __restrict__ adj)
{
    __shared__ float4 swk[HDIM / 4];
    int tid = threadIdx.x;
    if (tid < HDIM / 4)
        swk[tid] = ((const float4*)(w_att + HDIM))[tid];   // wk = w_att[0, H:2H]
    __syncthreads();

    int warp = tid >> 5, lane = tid & 31;
    int row0 = (blockIdx.x * 8 + warp) * 2;        // 16 rows per block

    const float4* kp0 = (const float4*)(Kmat + (size_t)row0 * HDIM);
    const float4* kp1 = kp0 + HDIM / 4;

    float4 a[4], c[4];
    #pragma unroll
    for (int i = 0; i < 4; i++) a[i] = kp0[lane + i * 32];
    #pragma unroll
    for (int i = 0; i < 4; i++) c[i] = kp1[lane + i * 32];

    float acc0 = 0.f, acc1 = 0.f;
    #pragma unroll
    for (int i = 0; i < 4; i++) {
        float4 w4 = swk[lane + i * 32];
        acc0 += a[i].x * w4.x + a[i].y * w4.y + a[i].z * w4.z + a[i].w * w4.w;
        acc1 += c[i].x * w4.x + c[i].y * w4.y + c[i].z * w4.z + c[i].w * w4.w;
    }
    #pragma unroll
    for (int o = 16; o > 0; o >>= 1) {
        acc0 += __shfl_xor_sync(0xFFFFFFFFu, acc0, o);
        acc1 += __shfl_xor_sync(0xFFFFFFFFu, acc1, o);
    }

    if (lane == 0) {
        float m0 = (float)adj[row0];
        float m1 = (float)adj[row0 + 1];
        g_alpha[row0]     = acc0 - (1.0f - m0) * MASK_NEG;
        g_alpha[row0 + 1] = acc1 - (1.0f - m1) * MASK_NEG;
    }
}

// ---------------------------------------------------------------------------
// K2: row softmax over N=2048 (one block per b) -> d_out[0 .. B*N).
// Also transposes Q into g_qT (free ride).
// ---------------------------------------------------------------------------
__global__ __launch_bounds__(1024)
void k_softmax(float* __restrict__ out_attn,
               const float* __restrict__ Q)
{
    __shared__ float sred[32];
    __shared__ float s_bm, s_bs;
    int b   = blockIdx.x;
    int tid = threadIdx.x;
    const float* a = g_alpha + b * NDIM;

    if (tid < HDIM)
        g_qT[tid * BDIM + b] = Q[b * HDIM + tid];

    float v0 = a[tid], v1 = a[tid + 1024];

    // block max
    float m = fmaxf(v0, v1);
    #pragma unroll
    for (int o = 16; o > 0; o >>= 1)
        m = fmaxf(m, __shfl_xor_sync(0xFFFFFFFFu, m, o));
    if ((tid & 31) == 0) sred[tid >> 5] = m;
    __syncthreads();
    if (tid < 32) {
        float t = sred[tid];
        #pragma unroll
        for (int o = 16; o > 0; o >>= 1)
            t = fmaxf(t, __shfl_xor_sync(0xFFFFFFFFu, t, o));
        if (tid == 0) s_bm = t;
    }
    __syncthreads();
    m = s_bm;

    float e0 = __expf(v0 - m), e1 = __expf(v1 - m);

    // block sum
    float s = e0 + e1;
    #pragma unroll
    for (int o = 16; o > 0; o >>= 1)
        s += __shfl_xor_sync(0xFFFFFFFFu, s, o);
    __syncthreads();
    if ((tid & 31) == 0) sred[tid >> 5] = s;
    __syncthreads();
    if (tid < 32) {
        float t = sred[tid];
        #pragma unroll
        for (int o = 16; o > 0; o >>= 1)
            t += __shfl_xor_sync(0xFFFFFFFFu, t, o);
        if (tid == 0) s_bs = t;
    }
    __syncthreads();
    float inv = 1.0f / s_bs;

    out_attn[b * NDIM + tid]        = e0 * inv;
    out_attn[b * NDIM + tid + 1024] = e1 * inv;
}

// ---------------------------------------------------------------------------
// K3: fused weighted V sum. Block = (b, slab of 32 h-floats).
// 512 threads = 64 n-groups x 8 float4-lanes. Each thread: 32 LDG.128 over
// its 32 rows, then block tree-reduce over groups -> writes y0T/y1T directly.
// Deterministic fixed-order reduction. Streams all of V (128 MiB), vectorized.
// ---------------------------------------------------------------------------
__global__ __launch_bounds__(512)
void k_wsum(const float* __restrict__ V,
            const int*   __restrict__ s_mask,
            const float* __restrict__ attn)
{
    __shared__ float  sw0[NDIM];
    __shared__ float  sw1[NDIM];
    __shared__ float4 red0[GROUPS][8];
    __shared__ float4 red1[GROUPS][8];

    int slab = blockIdx.x, b = blockIdx.y;
    int t  = threadIdx.x;
    int h4 = t & 7;          // float4 index within slab
    int g  = t >> 3;         // n-group

    // Stage attn*mask weights: 4 per thread, vectorized
    {
        float4 w = ((const float4*)(attn + b * NDIM))[t];
        int4   m = ((const int4*)(s_mask + b * NDIM))[t];
        int base = t * 4;
        float p;
        p = w.x * (float)m.x; sw0[base + 0] = p; sw1[base + 0] = w.x - p;
        p = w.y * (float)m.y; sw0[base + 1] = p; sw1[base + 1] = w.y - p;
        p = w.z * (float)m.z; sw0[base + 2] = p; sw1[base + 2] = w.z - p;
        p = w.w * (float)m.w; sw0[base + 3] = p; sw1[base + 3] = w.w - p;
    }
    __syncthreads();

    const float4* vp = (const float4*)(V + ((size_t)b * NDIM + g * RPG) * HDIM
                                         + slab * 32) + h4;
    const float* w0p = sw0 + g * RPG;
    const float* w1p = sw1 + g * RPG;

    float4 a0 = make_float4(0.f, 0.f, 0.f, 0.f);
    float4 a1 = make_float4(0.f, 0.f, 0.f, 0.f);
    #pragma unroll 8
    for (int n = 0; n < RPG; n++) {
        float4 v = vp[n * (HDIM / 4)];
        float c0 = w0p[n], c1 = w1p[n];
        a0.x += c0 * v.x; a0.y += c0 * v.y; a0.z += c0 * v.z; a0.w += c0 * v.w;
        a1.x += c1 * v.x; a1.y += c1 * v.y; a1.z += c1 * v.z; a1.w += c1 * v.w;
    }
    red0[g][h4] = a0;
    red1[g][h4] = a1;
    __syncthreads();

    // Deterministic tree reduce over the 64 groups
    #pragma unroll
    for (int s = GROUPS / 2; s > 0; s >>= 1) {
        if (g < s) {
            float4 x0 = red0[g][h4], y0 = red0[g + s][h4];
            float4 x1 = red1[g][h4], y1 = red1[g + s][h4];
            x0.x += y0.x; x0.y += y0.y; x0.z += y0.z; x0.w += y0.w;
            x1.x += y1.x; x1.y += y1.y; x1.z += y1.z; x1.w += y1.w;
            red0[g][h4] = x0;
            red1[g][h4] = x1;
        }
        __syncthreads();
    }

    if (t < 8) {
        float4 r0 = red0[0][t];
        float4 r1 = red1[0][t];
        int h = slab * 32 + t * 4;
        g_y0T[(h + 0) * BDIM + b] = r0.x;
        g_y0T[(h + 1) * BDIM + b] = r0.y;
        g_y0T[(h + 2) * BDIM + b] = r0.z;
        g_y0T[(h + 3) * BDIM + b] = r0.w;
        g_y1T[(h + 0) * BDIM + b] = r1.x;
        g_y1T[(h + 1) * BDIM + b] = r1.y;
        g_y1T[(h + 2) * BDIM + b] = r1.z;
        g_y1T[(h + 3) * BDIM + b] = r1.w;
    }
}

// ---------------------------------------------------------------------------
// K4: attn_sum[b,o] = sum_h Wr0[o,h]*y0[b,h] + Wr1[o,h]*y1[b,h] + Wri[o,h]*Q[b,h]
// One warp per output column o (lane = b); each W row read once chip-wide.
// ---------------------------------------------------------------------------
__global__ __launch_bounds__(256)
void k_final(const float* __restrict__ Wr0,
             const float* __restrict__ Wr1,
             const float* __restrict__ Wri,
             float* __restrict__ out)
{
    int warp = threadIdx.x >> 5, lane = threadIdx.x & 31;
    int o = blockIdx.x * 8 + warp;
    if (o >= HDIM) return;
    int b = lane;

    const float4* w0 = (const float4*)(Wr0 + (size_t)o * HDIM);
    const float4* w1 = (const float4*)(Wr1 + (size_t)o * HDIM);
    const float4* wi = (const float4*)(Wri + (size_t)o * HDIM);

    float acc = 0.f;
    #pragma unroll 4
    for (int h4 = 0; h4 < HDIM / 4; h4++) {
        float4 a = w0[h4];
        float4 c = w1[h4];
        float4 d = wi[h4];
        int h = h4 * 4;
        acc += a.x * g_y0T[(h + 0) * BDIM + b]
             + a.y * g_y0T[(h + 1) * BDIM + b]
             + a.z * g_y0T[(h + 2) * BDIM + b]
             + a.w * g_y0T[(h + 3) * BDIM + b];
        acc += c.x * g_y1T[(h + 0) * BDIM + b]
             + c.y * g_y1T[(h + 1) * BDIM + b]
             + c.z * g_y1T[(h + 2) * BDIM + b]
             + c.w * g_y1T[(h + 3) * BDIM + b];
        acc += d.x * g_qT[(h + 0) * BDIM + b]
             + d.y * g_qT[(h + 1) * BDIM + b]
             + d.z * g_qT[(h + 2) * BDIM + b]
             + d.w * g_qT[(h + 3) * BDIM + b];
    }
    out[BDIM * NDIM + b * HDIM + o] = acc;
}

// ---------------------------------------------------------------------------
// Launch. Inputs (metadata order): Q, K, V, adj, s_mask, w_att, b_att,
// Wr0, Wr1, Wri. Output: [attn (B*N) | attn_sum (B*H)] floats.
// ---------------------------------------------------------------------------
extern "C" void kernel_launch(void* const* d_in, const int* in_sizes, int n_in,
                              void* d_out, int out_size)
{
    const float* Q      = (const float*)d_in[0];
    const float* Kmat   = (const float*)d_in[1];
    const float* V      = (const float*)d_in[2];
    const int*   adj    = (const int*)  d_in[3];
    const int*   s_mask = (const int*)  d_in[4];
    const float* w_att  = (const float*)d_in[5];
    // d_in[6] = b_att (cancels in softmax; unused)
    const float* Wr0    = (const float*)d_in[7];
    const float* Wr1    = (const float*)d_in[8];
    const float* Wri    = (const float*)d_in[9];
    float* out = (float*)d_out;

    // K1: alpha, 16 rows per block
    k_alpha<<<(BDIM * NDIM) / 16, 256>>>(Kmat, w_att, adj);

    // K2: softmax per batch row (+ Q transpose), attn -> out[0 .. B*N)
    k_softmax<<<BDIM, 1024>>>(out, Q);

    // K3: fused weighted V sums -> y0T/y1T
    dim3 g3(SLABS, BDIM);
    k_wsum<<<g3, 512>>>(V, s_mask, out);

    // K4: final mini-GEMM -> out[B*N .. B*N + B*H)
    k_final<<<HDIM / 8, 256>>>(Wr0, Wr1, Wri, out);
}

// round 3
// speedup vs baseline: 2.4775x; 2.4775x over previous
#include <cuda_runtime.h>

// Problem constants (fixed shapes)
#define BDIM 32
#define NDIM 2048
#define HDIM 512
#define NCHUNK 16
#define CHUNK (NDIM / NCHUNK)   // 128
#define MASK_NEG 1e30f
#define OPB 2                   // output columns per k_final block

// Scratch (device globals: allowed; no runtime allocation)
__device__ float g_alpha[BDIM * NDIM];
__device__ float g_part0[BDIM * NCHUNK * HDIM];
__device__ float g_part1[BDIM * NCHUNK * HDIM];
__device__ float g_y0T[HDIM * BDIM];     // [h][b]
__device__ float g_y1T[HDIM * BDIM];     // [h][b]
__device__ float g_qT [HDIM * BDIM];     // [h][b]

// ---------------------------------------------------------------------------
// K1: alpha[b,n] = K[b,n,:] . wk - (1-adj)*1e30
// (Q.wq + b_att are per-row softmax constants -> skipped.)
// 2 rows per warp, 8 LDG.128 per lane issued up front.
// ---------------------------------------------------------------------------
__global__ __launch_bounds__(256)
void k_alpha(const float* __restrict__ Kmat,
             const float* __restrict__ w_att,
             const int*   __restrict__ adj)
{
    __shared__ float4 swk[HDIM / 4];
    int tid = threadIdx.x;
    if (tid < HDIM / 4)
        swk[tid] = ((const float4*)(w_att + HDIM))[tid];
    __syncthreads();

    int warp = tid >> 5, lane = tid & 31;
    int row0 = (blockIdx.x * 8 + warp) * 2;

    const float4* kp0 = (const float4*)(Kmat + (size_t)row0 * HDIM);
    const float4* kp1 = kp0 + HDIM / 4;

    float4 a[4], c[4];
    #pragma unroll
    for (int i = 0; i < 4; i++) a[i] = kp0[lane + i * 32];
    #pragma unroll
    for (int i = 0; i < 4; i++) c[i] = kp1[lane + i * 32];

    float acc0 = 0.f, acc1 = 0.f;
    #pragma unroll
    for (int i = 0; i < 4; i++) {
        float4 w4 = swk[lane + i * 32];
        acc0 += a[i].x * w4.x + a[i].y * w4.y + a[i].z * w4.z + a[i].w * w4.w;
        acc1 += c[i].x * w4.x + c[i].y * w4.y + c[i].z * w4.z + c[i].w * w4.w;
    }
    #pragma unroll
    for (int o = 16; o > 0; o >>= 1) {
        acc0 += __shfl_xor_sync(0xFFFFFFFFu, acc0, o);
        acc1 += __shfl_xor_sync(0xFFFFFFFFu, acc1, o);
    }

    if (lane == 0) {
        float m0 = (float)adj[row0];
        float m1 = (float)adj[row0 + 1];
        g_alpha[row0]     = acc0 - (1.0f - m0) * MASK_NEG;
        g_alpha[row0 + 1] = acc1 - (1.0f - m1) * MASK_NEG;
    }
}

// ---------------------------------------------------------------------------
// K2: row softmax over N=2048 (one block per b) -> d_out[0 .. B*N).
// Also transposes Q into g_qT.
// ---------------------------------------------------------------------------
__global__ __launch_bounds__(1024)
void k_softmax(float* __restrict__ out_attn,
               const float* __restrict__ Q)
{
    __shared__ float sred[32];
    __shared__ float s_bm, s_bs;
    int b   = blockIdx.x;
    int tid = threadIdx.x;
    const float* a = g_alpha + b * NDIM;

    if (tid < HDIM)
        g_qT[tid * BDIM + b] = Q[b * HDIM + tid];

    float v0 = a[tid], v1 = a[tid + 1024];

    float m = fmaxf(v0, v1);
    #pragma unroll
    for (int o = 16; o > 0; o >>= 1)
        m = fmaxf(m, __shfl_xor_sync(0xFFFFFFFFu, m, o));
    if ((tid & 31) == 0) sred[tid >> 5] = m;
    __syncthreads();
    if (tid < 32) {
        float t = sred[tid];
        #pragma unroll
        for (int o = 16; o > 0; o >>= 1)
            t = fmaxf(t, __shfl_xor_sync(0xFFFFFFFFu, t, o));
        if (tid == 0) s_bm = t;
    }
    __syncthreads();
    m = s_bm;

    float e0 = __expf(v0 - m), e1 = __expf(v1 - m);

    float s = e0 + e1;
    #pragma unroll
    for (int o = 16; o > 0; o >>= 1)
        s += __shfl_xor_sync(0xFFFFFFFFu, s, o);
    __syncthreads();
    if ((tid & 31) == 0) sred[tid >> 5] = s;
    __syncthreads();
    if (tid < 32) {
        float t = sred[tid];
        #pragma unroll
        for (int o = 16; o > 0; o >>= 1)
            t += __shfl_xor_sync(0xFFFFFFFFu, t, o);
        if (tid == 0) s_bs = t;
    }
    __syncthreads();
    float inv = 1.0f / s_bs;

    out_attn[b * NDIM + tid]        = e0 * inv;
    out_attn[b * NDIM + tid + 1024] = e1 * inv;
}

// ---------------------------------------------------------------------------
// K3: partial weighted V sums (proven R1 design). grid (NCHUNK, B), 512 thr.
// ---------------------------------------------------------------------------
__global__ __launch_bounds__(512)
void k_wsum(const float* __restrict__ V,
            const int*   __restrict__ s_mask,
            const float* __restrict__ attn)
{
    __shared__ float sw0[CHUNK];
    __shared__ float sw1[CHUNK];
    int c = blockIdx.x, b = blockIdx.y;
    int t = threadIdx.x;
    int n0 = c * CHUNK;

    if (t < CHUNK) {
        float w   = attn[b * NDIM + n0 + t];
        float smf = (float)s_mask[b * NDIM + n0 + t];
        float ws  = w * smf;
        sw0[t] = ws;
        sw1[t] = w - ws;
    }
    __syncthreads();

    const float* vp = V + ((size_t)b * NDIM + n0) * HDIM + t;
    float a0 = 0.f, a1 = 0.f;
    #pragma unroll 8
    for (int n = 0; n < CHUNK; n++) {
        float v = vp[(size_t)n * HDIM];
        a0 += sw0[n] * v;
        a1 += sw1[n] * v;
    }
    g_part0[(b * NCHUNK + c) * HDIM + t] = a0;
    g_part1[(b * NCHUNK + c) * HDIM + t] = a1;
}

// ---------------------------------------------------------------------------
// K4: reduce partials over chunks (vectorized), write transposed.
// grid = BDIM, 128 threads, float4 per thread.
// ---------------------------------------------------------------------------
__global__ __launch_bounds__(128)
void k_reduce()
{
    int b  = blockIdx.x;
    int t  = threadIdx.x;          // float4 index within HDIM/4 = 128

    float4 s0 = make_float4(0.f, 0.f, 0.f, 0.f);
    float4 s1 = make_float4(0.f, 0.f, 0.f, 0.f);
    #pragma unroll
    for (int c = 0; c < NCHUNK; c++) {
        float4 p0 = ((const float4*)(g_part0 + (b * NCHUNK + c) * HDIM))[t];
        float4 p1 = ((const float4*)(g_part1 + (b * NCHUNK + c) * HDIM))[t];
        s0.x += p0.x; s0.y += p0.y; s0.z += p0.z; s0.w += p0.w;
        s1.x += p1.x; s1.y += p1.y; s1.z += p1.z; s1.w += p1.w;
    }
    int h = t * 4;
    g_y0T[(h + 0) * BDIM + b] = s0.x;
    g_y0T[(h + 1) * BDIM + b] = s0.y;
    g_y0T[(h + 2) * BDIM + b] = s0.z;
    g_y0T[(h + 3) * BDIM + b] = s0.w;
    g_y1T[(h + 0) * BDIM + b] = s1.x;
    g_y1T[(h + 1) * BDIM + b] = s1.y;
    g_y1T[(h + 2) * BDIM + b] = s1.z;
    g_y1T[(h + 3) * BDIM + b] = s1.w;
}

// ---------------------------------------------------------------------------
// K5: attn_sum[b,o] = sum_h Wr0[o,h]*y0[b,h] + Wr1[o,h]*y1[b,h] + Wri[o,h]*Q[b,h]
// Grid = HDIM/OPB blocks, 256 threads. Weights staged in smem; warp = 64-h
// chunk, lane = b. 192 independent coalesced LDGs per thread; deterministic
// smem reduce over 8 warps.
// ---------------------------------------------------------------------------
__global__ __launch_bounds__(256)
void k_final(const float* __restrict__ Wr0,
             const float* __restrict__ Wr1,
             const float* __restrict__ Wri,
             float* __restrict__ out)
{
    __shared__ float sw[OPB][3 * HDIM];        // per-o: [wr0 | wr1 | wri]
    __shared__ float red[OPB][8][BDIM];

    int t  = threadIdx.x;
    int o0 = blockIdx.x * OPB;

    // Stage OPB*3 weight rows, float4-coalesced: OPB*3*HDIM/4 = 768 float4
    #pragma unroll
    for (int i = t; i < OPB * 3 * (HDIM / 4); i += 256) {
        int o     = i / (3 * (HDIM / 4));
        int r     = i % (3 * (HDIM / 4));
        int which = r / (HDIM / 4);
        int j     = r % (HDIM / 4);
        const float* src = (which == 0) ? Wr0 : (which == 1) ? Wr1 : Wri;
        ((float4*)sw[o])[r] = ((const float4*)(src + (size_t)(o0 + o) * HDIM))[j];
    }
    __syncthreads();

    int warp = t >> 5, b = t & 31;
    int h0 = warp * 64;

    float acc0 = 0.f, acc1 = 0.f;
    #pragma unroll 8
    for (int i = 0; i < 64; i++) {
        int h = h0 + i;
        float x0 = g_y0T[h * BDIM + b];
        float x1 = g_y1T[h * BDIM + b];
        float xq = g_qT [h * BDIM + b];
        acc0 += sw[0][h] * x0 + sw[0][HDIM + h] * x1 + sw[0][2 * HDIM + h] * xq;
        acc1 += sw[1][h] * x0 + sw[1][HDIM + h] * x1 + sw[1][2 * HDIM + h] * xq;
    }
    red[0][warp][b] = acc0;
    red[1][warp][b] = acc1;
    __syncthreads();

    if (t < BDIM * OPB) {
        int o  = t >> 5;
        int b2 = t & 31;
        float s = 0.f;
        #pragma unroll
        for (int w = 0; w < 8; w++) s += red[o][w][b2];
        out[BDIM * NDIM + b2 * HDIM + (o0 + o)] = s;
    }
}

// ---------------------------------------------------------------------------
// Launch. Inputs: Q, K, V, adj, s_mask, w_att, b_att, Wr0, Wr1, Wri.
// Output: [attn (B*N) | attn_sum (B*H)] floats.
// ---------------------------------------------------------------------------
extern "C" void kernel_launch(void* const* d_in, const int* in_sizes, int n_in,
                              void* d_out, int out_size)
{
    const float* Q      = (const float*)d_in[0];
    const float* Kmat   = (const float*)d_in[1];
    const float* V      = (const float*)d_in[2];
    const int*   adj    = (const int*)  d_in[3];
    const int*   s_mask = (const int*)  d_in[4];
    const float* w_att  = (const float*)d_in[5];
    // d_in[6] = b_att (cancels in softmax)
    const float* Wr0    = (const float*)d_in[7];
    const float* Wr1    = (const float*)d_in[8];
    const float* Wri    = (const float*)d_in[9];
    float* out = (float*)d_out;

    k_alpha<<<(BDIM * NDIM) / 16, 256>>>(Kmat, w_att, adj);
    k_softmax<<<BDIM, 1024>>>(out, Q);
    dim3 g3(NCHUNK, BDIM);
    k_wsum<<<g3, 512>>>(V, s_mask, out);
    k_reduce<<<BDIM, 128>>>();
    k_final<<<HDIM / OPB, 256>>>(Wr0, Wr1, Wri, out);
}

// round 4
// speedup vs baseline: 2.5459x; 1.0276x over previous
#include <cuda_runtime.h>

// Problem constants (fixed shapes)
#define BDIM 32
#define NDIM 2048
#define HDIM 512
#define NCHUNK 16
#define CHUNK (NDIM / NCHUNK)   // 128
#define MASK_NEG 1e30f
#define OPB 2                   // output columns per k_final block

// Scratch (device globals: allowed; no runtime allocation)
__device__ float g_alpha[BDIM * NDIM];
__device__ float g_part0[BDIM * NCHUNK * HDIM];
__device__ float g_part1[BDIM * NCHUNK * HDIM];
__device__ float g_y0T[HDIM * BDIM];     // [h][b]
__device__ float g_y1T[HDIM * BDIM];     // [h][b]
__device__ float g_qT [HDIM * BDIM];     // [h][b]

// ---------------------------------------------------------------------------
// K1: alpha[b,n] = K[b,n,:] . wk - (1-adj)*1e30
// (Q.wq + b_att are per-row softmax constants -> skipped.)
// 2 rows per warp, 8 LDG.128 per lane issued up front.
// ---------------------------------------------------------------------------
__global__ __launch_bounds__(256)
void k_alpha(const float* __restrict__ Kmat,
             const float* __restrict__ w_att,
             const int*   __restrict__ adj)
{
    __shared__ float4 swk[HDIM / 4];
    int tid = threadIdx.x;
    if (tid < HDIM / 4)
        swk[tid] = ((const float4*)(w_att + HDIM))[tid];
    __syncthreads();

    int warp = tid >> 5, lane = tid & 31;
    int row0 = (blockIdx.x * 8 + warp) * 2;

    const float4* kp0 = (const float4*)(Kmat + (size_t)row0 * HDIM);
    const float4* kp1 = kp0 + HDIM / 4;

    float4 a[4], c[4];
    #pragma unroll
    for (int i = 0; i < 4; i++) a[i] = kp0[lane + i * 32];
    #pragma unroll
    for (int i = 0; i < 4; i++) c[i] = kp1[lane + i * 32];

    float acc0 = 0.f, acc1 = 0.f;
    #pragma unroll
    for (int i = 0; i < 4; i++) {
        float4 w4 = swk[lane + i * 32];
        acc0 += a[i].x * w4.x + a[i].y * w4.y + a[i].z * w4.z + a[i].w * w4.w;
        acc1 += c[i].x * w4.x + c[i].y * w4.y + c[i].z * w4.z + c[i].w * w4.w;
    }
    #pragma unroll
    for (int o = 16; o > 0; o >>= 1) {
        acc0 += __shfl_xor_sync(0xFFFFFFFFu, acc0, o);
        acc1 += __shfl_xor_sync(0xFFFFFFFFu, acc1, o);
    }

    if (lane == 0) {
        float m0 = (float)adj[row0];
        float m1 = (float)adj[row0 + 1];
        g_alpha[row0]     = acc0 - (1.0f - m0) * MASK_NEG;
        g_alpha[row0 + 1] = acc1 - (1.0f - m1) * MASK_NEG;
    }
}

// ---------------------------------------------------------------------------
// K2: row softmax over N=2048 (one block per b) -> d_out[0 .. B*N).
// Also transposes Q into g_qT.
// ---------------------------------------------------------------------------
__global__ __launch_bounds__(1024)
void k_softmax(float* __restrict__ out_attn,
               const float* __restrict__ Q)
{
    __shared__ float sred[32];
    __shared__ float s_bm, s_bs;
    int b   = blockIdx.x;
    int tid = threadIdx.x;
    const float* a = g_alpha + b * NDIM;

    if (tid < HDIM)
        g_qT[tid * BDIM + b] = Q[b * HDIM + tid];

    float v0 = a[tid], v1 = a[tid + 1024];

    float m = fmaxf(v0, v1);
    #pragma unroll
    for (int o = 16; o > 0; o >>= 1)
        m = fmaxf(m, __shfl_xor_sync(0xFFFFFFFFu, m, o));
    if ((tid & 31) == 0) sred[tid >> 5] = m;
    __syncthreads();
    if (tid < 32) {
        float t = sred[tid];
        #pragma unroll
        for (int o = 16; o > 0; o >>= 1)
            t = fmaxf(t, __shfl_xor_sync(0xFFFFFFFFu, t, o));
        if (tid == 0) s_bm = t;
    }
    __syncthreads();
    m = s_bm;

    float e0 = __expf(v0 - m), e1 = __expf(v1 - m);

    float s = e0 + e1;
    #pragma unroll
    for (int o = 16; o > 0; o >>= 1)
        s += __shfl_xor_sync(0xFFFFFFFFu, s, o);
    __syncthreads();
    if ((tid & 31) == 0) sred[tid >> 5] = s;
    __syncthreads();
    if (tid < 32) {
        float t = sred[tid];
        #pragma unroll
        for (int o = 16; o > 0; o >>= 1)
            t += __shfl_xor_sync(0xFFFFFFFFu, t, o);
        if (tid == 0) s_bs = t;
    }
    __syncthreads();
    float inv = 1.0f / s_bs;

    out_attn[b * NDIM + tid]        = e0 * inv;
    out_attn[b * NDIM + tid + 1024] = e1 * inv;
}

// ---------------------------------------------------------------------------
// K3: partial weighted V sums, float4-vectorized.
// grid (NCHUNK, B), 512 threads = 128 float4-lanes x 4 n-subgroups.
// Each thread: 32 independent LDG.128 over its 32 rows; deterministic smem
// combine over the 4 subgroups; writes per-chunk partials as float4.
// ---------------------------------------------------------------------------
__global__ __launch_bounds__(512)
void k_wsum(const float* __restrict__ V,
            const int*   __restrict__ s_mask,
            const float* __restrict__ attn)
{
    __shared__ float  sw0[CHUNK];
    __shared__ float  sw1[CHUNK];
    __shared__ float4 red0[4][HDIM / 4];
    __shared__ float4 red1[4][HDIM / 4];

    int c = blockIdx.x, b = blockIdx.y;
    int t  = threadIdx.x;
    int f4 = t & 127;        // float4 lane within HDIM/4
    int sg = t >> 7;         // n-subgroup (0..3), 32 rows each
    int n0 = c * CHUNK;

    if (t < CHUNK) {
        float w   = attn[b * NDIM + n0 + t];
        float smf = (float)s_mask[b * NDIM + n0 + t];
        float ws  = w * smf;
        sw0[t] = ws;
        sw1[t] = w - ws;
    }
    __syncthreads();

    const float4* vp = (const float4*)(V + ((size_t)b * NDIM + n0 + sg * 32) * HDIM) + f4;
    const float* w0p = sw0 + sg * 32;
    const float* w1p = sw1 + sg * 32;

    float4 a0 = make_float4(0.f, 0.f, 0.f, 0.f);
    float4 a1 = make_float4(0.f, 0.f, 0.f, 0.f);
    #pragma unroll 8
    for (int n = 0; n < 32; n++) {
        float4 v = vp[n * (HDIM / 4)];
        float c0 = w0p[n], c1 = w1p[n];
        a0.x += c0 * v.x; a0.y += c0 * v.y; a0.z += c0 * v.z; a0.w += c0 * v.w;
        a1.x += c1 * v.x; a1.y += c1 * v.y; a1.z += c1 * v.z; a1.w += c1 * v.w;
    }
    red0[sg][f4] = a0;
    red1[sg][f4] = a1;
    __syncthreads();

    if (t < HDIM / 4) {
        float4 s0 = red0[0][t], s1 = red1[0][t];
        #pragma unroll
        for (int g = 1; g < 4; g++) {
            float4 p0 = red0[g][t], p1 = red1[g][t];
            s0.x += p0.x; s0.y += p0.y; s0.z += p0.z; s0.w += p0.w;
            s1.x += p1.x; s1.y += p1.y; s1.z += p1.z; s1.w += p1.w;
        }
        ((float4*)(g_part0 + (b * NCHUNK + c) * HDIM))[t] = s0;
        ((float4*)(g_part1 + (b * NCHUNK + c) * HDIM))[t] = s1;
    }
}

// ---------------------------------------------------------------------------
// K4: reduce partials over chunks. grid (B, 4 h-slabs), 128 threads =
// 32 float4-lanes x 4 chunk-groups; 8 loads/thread; deterministic combine.
// ---------------------------------------------------------------------------
__global__ __launch_bounds__(128)
void k_reduce()
{
    __shared__ float4 red0[4][32];
    __shared__ float4 red1[4][32];

    int b    = blockIdx.x;
    int slab = blockIdx.y;           // h-quarter: 32 float4 = 128 h
    int t    = threadIdx.x;
    int f4l  = t & 31;
    int cg   = t >> 5;               // chunk-group (0..3), 4 chunks each
    int f4   = slab * 32 + f4l;

    float4 s0 = make_float4(0.f, 0.f, 0.f, 0.f);
    float4 s1 = make_float4(0.f, 0.f, 0.f, 0.f);
    #pragma unroll
    for (int i = 0; i < 4; i++) {
        int c = cg * 4 + i;
        float4 p0 = ((const float4*)(g_part0 + (b * NCHUNK + c) * HDIM))[f4];
        float4 p1 = ((const float4*)(g_part1 + (b * NCHUNK + c) * HDIM))[f4];
        s0.x += p0.x; s0.y += p0.y; s0.z += p0.z; s0.w += p0.w;
        s1.x += p1.x; s1.y += p1.y; s1.z += p1.z; s1.w += p1.w;
    }
    red0[cg][f4l] = s0;
    red1[cg][f4l] = s1;
    __syncthreads();

    if (t < 32) {
        float4 r0 = red0[0][t], r1 = red1[0][t];
        #pragma unroll
        for (int g = 1; g < 4; g++) {
            float4 p0 = red0[g][t], p1 = red1[g][t];
            r0.x += p0.x; r0.y += p0.y; r0.z += p0.z; r0.w += p0.w;
            r1.x += p1.x; r1.y += p1.y; r1.z += p1.z; r1.w += p1.w;
        }
        int h = (slab * 32 + t) * 4;
        g_y0T[(h + 0) * BDIM + b] = r0.x;
        g_y0T[(h + 1) * BDIM + b] = r0.y;
        g_y0T[(h + 2) * BDIM + b] = r0.z;
        g_y0T[(h + 3) * BDIM + b] = r0.w;
        g_y1T[(h + 0) * BDIM + b] = r1.x;
        g_y1T[(h + 1) * BDIM + b] = r1.y;
        g_y1T[(h + 2) * BDIM + b] = r1.z;
        g_y1T[(h + 3) * BDIM + b] = r1.w;
    }
}

// ---------------------------------------------------------------------------
// K5: attn_sum[b,o] = sum_h Wr0[o,h]*y0[b,h] + Wr1[o,h]*y1[b,h] + Wri[o,h]*Q[b,h]
// Grid = HDIM/OPB blocks, 256 threads. Weights staged in smem; warp = 64-h
// chunk, lane = b. Deterministic smem reduce over 8 warps.
// ---------------------------------------------------------------------------
__global__ __launch_bounds__(256)
void k_final(const float* __restrict__ Wr0,
             const float* __restrict__ Wr1,
             const float* __restrict__ Wri,
             float* __restrict__ out)
{
    __shared__ float sw[OPB][3 * HDIM];        // per-o: [wr0 | wr1 | wri]
    __shared__ float red[OPB][8][BDIM];

    int t  = threadIdx.x;
    int o0 = blockIdx.x * OPB;

    #pragma unroll
    for (int i = t; i < OPB * 3 * (HDIM / 4); i += 256) {
        int o     = i / (3 * (HDIM / 4));
        int r     = i % (3 * (HDIM / 4));
        int which = r / (HDIM / 4);
        int j     = r % (HDIM / 4);
        const float* src = (which == 0) ? Wr0 : (which == 1) ? Wr1 : Wri;
        ((float4*)sw[o])[r] = ((const float4*)(src + (size_t)(o0 + o) * HDIM))[j];
    }
    __syncthreads();

    int warp = t >> 5, b = t & 31;
    int h0 = warp * 64;

    float acc0 = 0.f, acc1 = 0.f;
    #pragma unroll 8
    for (int i = 0; i < 64; i++) {
        int h = h0 + i;
        float x0 = g_y0T[h * BDIM + b];
        float x1 = g_y1T[h * BDIM + b];
        float xq = g_qT [h * BDIM + b];
        acc0 += sw[0][h] * x0 + sw[0][HDIM + h] * x1 + sw[0][2 * HDIM + h] * xq;
        acc1 += sw[1][h] * x0 + sw[1][HDIM + h] * x1 + sw[1][2 * HDIM + h] * xq;
    }
    red[0][warp][b] = acc0;
    red[1][warp][b] = acc1;
    __syncthreads();

    if (t < BDIM * OPB) {
        int o  = t >> 5;
        int b2 = t & 31;
        float s = 0.f;
        #pragma unroll
        for (int w = 0; w < 8; w++) s += red[o][w][b2];
        out[BDIM * NDIM + b2 * HDIM + (o0 + o)] = s;
    }
}

// ---------------------------------------------------------------------------
// Launch. Inputs: Q, K, V, adj, s_mask, w_att, b_att, Wr0, Wr1, Wri.
// Output: [attn (B*N) | attn_sum (B*H)] floats.
// ---------------------------------------------------------------------------
extern "C" void kernel_launch(void* const* d_in, const int* in_sizes, int n_in,
                              void* d_out, int out_size)
{
    const float* Q      = (const float*)d_in[0];
    const float* Kmat   = (const float*)d_in[1];
    const float* V      = (const float*)d_in[2];
    const int*   adj    = (const int*)  d_in[3];
    const int*   s_mask = (const int*)  d_in[4];
    const float* w_att  = (const float*)d_in[5];
    // d_in[6] = b_att (cancels in softmax)
    const float* Wr0    = (const float*)d_in[7];
    const float* Wr1    = (const float*)d_in[8];
    const float* Wri    = (const float*)d_in[9];
    float* out = (float*)d_out;

    k_alpha<<<(BDIM * NDIM) / 16, 256>>>(Kmat, w_att, adj);
    k_softmax<<<BDIM, 1024>>>(out, Q);
    dim3 g3(NCHUNK, BDIM);
    k_wsum<<<g3, 512>>>(V, s_mask, out);
    dim3 g4(BDIM, 4);
    k_reduce<<<g4, 128>>>();
    k_final<<<HDIM / OPB, 256>>>(Wr0, Wr1, Wri, out);
}

// round 7
// speedup vs baseline: 2.6947x; 1.0584x over previous
#include <cuda_runtime.h>

// Problem constants (fixed shapes)
#define BDIM 32
#define NDIM 2048
#define HDIM 512
#define NCHUNK 16
#define CHUNK (NDIM / NCHUNK)   // 128
#define MASK_NEG 1e30f
#define OPB 4                   // output columns per k_final block

// Scratch (device globals: allowed; no runtime allocation)
__device__ float g_alpha[BDIM * NDIM];
__device__ float g_part0[BDIM * NCHUNK * HDIM];
__device__ float g_part1[BDIM * NCHUNK * HDIM];
__device__ float g_y0T[HDIM * BDIM];     // [h][b]
__device__ float g_y1T[HDIM * BDIM];     // [h][b]
__device__ float g_qT [HDIM * BDIM];     // [h][b]
__device__ int   g_cnt[BDIM];            // zero-init; self-resetting

// ---------------------------------------------------------------------------
// K1: alpha[b,n] = K[b,n,:] . wk - (1-adj)*1e30
// (Q.wq + b_att are per-row softmax constants -> skipped.)
// 2 rows per warp, 8 LDG.128 per lane issued up front.
// ---------------------------------------------------------------------------
__global__ __launch_bounds__(256)
void k_alpha(const float* __restrict__ Kmat,
             const float* __restrict__ w_att,
             const int*   __restrict__ adj)
{
    __shared__ float4 swk[HDIM / 4];
    int tid = threadIdx.x;
    if (tid < HDIM / 4)
        swk[tid] = ((const float4*)(w_att + HDIM))[tid];
    __syncthreads();

    int warp = tid >> 5, lane = tid & 31;
    int row0 = (blockIdx.x * 8 + warp) * 2;

    const float4* kp0 = (const float4*)(Kmat + (size_t)row0 * HDIM);
    const float4* kp1 = kp0 + HDIM / 4;

    float4 a[4], c[4];
    #pragma unroll
    for (int i = 0; i < 4; i++) a[i] = kp0[lane + i * 32];
    #pragma unroll
    for (int i = 0; i < 4; i++) c[i] = kp1[lane + i * 32];

    float acc0 = 0.f, acc1 = 0.f;
    #pragma unroll
    for (int i = 0; i < 4; i++) {
        float4 w4 = swk[lane + i * 32];
        acc0 += a[i].x * w4.x + a[i].y * w4.y + a[i].z * w4.z + a[i].w * w4.w;
        acc1 += c[i].x * w4.x + c[i].y * w4.y + c[i].z * w4.z + c[i].w * w4.w;
    }
    #pragma unroll
    for (int o = 16; o > 0; o >>= 1) {
        acc0 += __shfl_xor_sync(0xFFFFFFFFu, acc0, o);
        acc1 += __shfl_xor_sync(0xFFFFFFFFu, acc1, o);
    }

    if (lane == 0) {
        float m0 = (float)adj[row0];
        float m1 = (float)adj[row0 + 1];
        g_alpha[row0]     = acc0 - (1.0f - m0) * MASK_NEG;
        g_alpha[row0 + 1] = acc1 - (1.0f - m1) * MASK_NEG;
    }
}

// ---------------------------------------------------------------------------
// K2: row softmax over N=2048 (one block per b) -> d_out[0 .. B*N).
// Also transposes Q into g_qT.
// ---------------------------------------------------------------------------
__global__ __launch_bounds__(1024)
void k_softmax(float* __restrict__ out_attn,
               const float* __restrict__ Q)
{
    __shared__ float sred[32];
    __shared__ float s_bm, s_bs;
    int b   = blockIdx.x;
    int tid = threadIdx.x;
    const float* a = g_alpha + b * NDIM;

    if (tid < HDIM)
        g_qT[tid * BDIM + b] = Q[b * HDIM + tid];

    float v0 = a[tid], v1 = a[tid + 1024];

    float m = fmaxf(v0, v1);
    #pragma unroll
    for (int o = 16; o > 0; o >>= 1)
        m = fmaxf(m, __shfl_xor_sync(0xFFFFFFFFu, m, o));
    if ((tid & 31) == 0) sred[tid >> 5] = m;
    __syncthreads();
    if (tid < 32) {
        float t = sred[tid];
        #pragma unroll
        for (int o = 16; o > 0; o >>= 1)
            t = fmaxf(t, __shfl_xor_sync(0xFFFFFFFFu, t, o));
        if (tid == 0) s_bm = t;
    }
    __syncthreads();
    m = s_bm;

    float e0 = __expf(v0 - m), e1 = __expf(v1 - m);

    float s = e0 + e1;
    #pragma unroll
    for (int o = 16; o > 0; o >>= 1)
        s += __shfl_xor_sync(0xFFFFFFFFu, s, o);
    __syncthreads();
    if ((tid & 31) == 0) sred[tid >> 5] = s;
    __syncthreads();
    if (tid < 32) {
        float t = sred[tid];
        #pragma unroll
        for (int o = 16; o > 0; o >>= 1)
            t += __shfl_xor_sync(0xFFFFFFFFu, t, o);
        if (tid == 0) s_bs = t;
    }
    __syncthreads();
    float inv = 1.0f / s_bs;

    out_attn[b * NDIM + tid]        = e0 * inv;
    out_attn[b * NDIM + tid + 1024] = e1 * inv;
}

// ---------------------------------------------------------------------------
// K3: partial weighted V sums + fused last-block chunk reduce.
// grid (NCHUNK, B), 512 threads = 128 float4-lanes x 4 n-subgroups.
// Last chunk-block per b (atomic counter) reduces all 16 partials in fixed
// deterministic order and writes y0T/y1T; counter self-resets.
// ---------------------------------------------------------------------------
__global__ __launch_bounds__(512)
void k_wsum(const float* __restrict__ V,
            const int*   __restrict__ s_mask,
            const float* __restrict__ attn)
{
    __shared__ float  sw0[CHUNK];
    __shared__ float  sw1[CHUNK];
    __shared__ float4 red0[4][HDIM / 4];
    __shared__ float4 red1[4][HDIM / 4];
    __shared__ int    s_last;

    int c = blockIdx.x, b = blockIdx.y;
    int t  = threadIdx.x;
    int f4 = t & 127;        // float4 lane within HDIM/4
    int sg = t >> 7;         // n-subgroup (0..3), 32 rows each
    int n0 = c * CHUNK;

    if (t < CHUNK) {
        float w   = attn[b * NDIM + n0 + t];
        float smf = (float)s_mask[b * NDIM + n0 + t];
        float ws  = w * smf;
        sw0[t] = ws;
        sw1[t] = w - ws;
    }
    __syncthreads();

    const float4* vp = (const float4*)(V + ((size_t)b * NDIM + n0 + sg * 32) * HDIM) + f4;
    const float* w0p = sw0 + sg * 32;
    const float* w1p = sw1 + sg * 32;

    float4 a0 = make_float4(0.f, 0.f, 0.f, 0.f);
    float4 a1 = make_float4(0.f, 0.f, 0.f, 0.f);
    #pragma unroll 8
    for (int n = 0; n < 32; n++) {
        float4 v = vp[n * (HDIM / 4)];
        float c0 = w0p[n], c1 = w1p[n];
        a0.x += c0 * v.x; a0.y += c0 * v.y; a0.z += c0 * v.z; a0.w += c0 * v.w;
        a1.x += c1 * v.x; a1.y += c1 * v.y; a1.z += c1 * v.z; a1.w += c1 * v.w;
    }
    red0[sg][f4] = a0;
    red1[sg][f4] = a1;
    __syncthreads();

    if (t < HDIM / 4) {
        float4 s0 = red0[0][t], s1 = red1[0][t];
        #pragma unroll
        for (int g = 1; g < 4; g++) {
            float4 p0 = red0[g][t], p1 = red1[g][t];
            s0.x += p0.x; s0.y += p0.y; s0.z += p0.z; s0.w += p0.w;
            s1.x += p1.x; s1.y += p1.y; s1.z += p1.z; s1.w += p1.w;
        }
        ((float4*)(g_part0 + (b * NCHUNK + c) * HDIM))[t] = s0;
        ((float4*)(g_part1 + (b * NCHUNK + c) * HDIM))[t] = s1;
    }

    // --- fused cross-chunk reduce: last block per b does it ---
    __threadfence();
    __syncthreads();
    if (t == 0) {
        int v = atomicAdd(&g_cnt[b], 1);
        s_last = (v == NCHUNK - 1) ? 1 : 0;
    }
    __syncthreads();
    if (!s_last) return;
    __threadfence();   // acquire: make other blocks' partials visible

    // 512 threads = 128 f4-lanes x 4 chunk-groups; fixed-order combine
    int cg = t >> 7;   // chunk-group (0..3), 4 chunks each
    {
        float4 s0 = make_float4(0.f, 0.f, 0.f, 0.f);
        float4 s1 = make_float4(0.f, 0.f, 0.f, 0.f);
        #pragma unroll
        for (int i = 0; i < 4; i++) {
            int cc = cg * 4 + i;
            float4 p0 = ((const float4*)(g_part0 + (b * NCHUNK + cc) * HDIM))[f4];
            float4 p1 = ((const float4*)(g_part1 + (b * NCHUNK + cc) * HDIM))[f4];
            s0.x += p0.x; s0.y += p0.y; s0.z += p0.z; s0.w += p0.w;
            s1.x += p1.x; s1.y += p1.y; s1.z += p1.z; s1.w += p1.w;
        }
        red0[cg][f4] = s0;
        red1[cg][f4] = s1;
    }
    __syncthreads();

    if (t < HDIM / 4) {
        float4 r0 = red0[0][t], r1 = red1[0][t];
        #pragma unroll
        for (int g = 1; g < 4; g++) {
            float4 p0 = red0[g][t], p1 = red1[g][t];
            r0.x += p0.x; r0.y += p0.y; r0.z += p0.z; r0.w += p0.w;
            r1.x += p1.x; r1.y += p1.y; r1.z += p1.z; r1.w += p1.w;
        }
        int h = t * 4;
        g_y0T[(h + 0) * BDIM + b] = r0.x;
        g_y0T[(h + 1) * BDIM + b] = r0.y;
        g_y0T[(h + 2) * BDIM + b] = r0.z;
        g_y0T[(h + 3) * BDIM + b] = r0.w;
        g_y1T[(h + 0) * BDIM + b] = r1.x;
        g_y1T[(h + 1) * BDIM + b] = r1.y;
        g_y1T[(h + 2) * BDIM + b] = r1.z;
        g_y1T[(h + 3) * BDIM + b] = r1.w;
    }
    if (t == 0) g_cnt[b] = 0;   // self-reset for next graph replay
}

// ---------------------------------------------------------------------------
// K4: attn_sum[b,o] = sum_h Wr0[o,h]*y0[b,h] + Wr1[o,h]*y1[b,h] + Wri[o,h]*Q[b,h]
// Grid = HDIM/OPB = 128 blocks, 256 threads. 4 output columns per block:
// y-gather traffic amortized 4x. Weights staged in smem (24 KB).
// ---------------------------------------------------------------------------
__global__ __launch_bounds__(256)
void k_final(const float* __restrict__ Wr0,
             const float* __restrict__ Wr1,
             const float* __restrict__ Wri,
             float* __restrict__ out)
{
    __shared__ float sw[OPB][3 * HDIM];        // per-o: [wr0 | wr1 | wri]
    __shared__ float red[OPB][8][BDIM];

    int t  = threadIdx.x;
    int o0 = blockIdx.x * OPB;

    #pragma unroll
    for (int i = t; i < OPB * 3 * (HDIM / 4); i += 256) {
        int o     = i / (3 * (HDIM / 4));
        int r     = i % (3 * (HDIM / 4));
        int which = r / (HDIM / 4);
        int j     = r % (HDIM / 4);
        const float* src = (which == 0) ? Wr0 : (which == 1) ? Wr1 : Wri;
        ((float4*)sw[o])[r] = ((const float4*)(src + (size_t)(o0 + o) * HDIM))[j];
    }
    __syncthreads();

    int warp = t >> 5, b = t & 31;
    int h0 = warp * 64;

    float acc0 = 0.f, acc1 = 0.f, acc2 = 0.f, acc3 = 0.f;
    #pragma unroll 8
    for (int i = 0; i < 64; i++) {
        int h = h0 + i;
        float x0 = g_y0T[h * BDIM + b];
        float x1 = g_y1T[h * BDIM + b];
        float xq = g_qT [h * BDIM + b];
        acc0 += sw[0][h] * x0 + sw[0][HDIM + h] * x1 + sw[0][2 * HDIM + h] * xq;
        acc1 += sw[1][h] * x0 + sw[1][HDIM + h] * x1 + sw[1][2 * HDIM + h] * xq;
        acc2 += sw[2][h] * x0 + sw[2][HDIM + h] * x1 + sw[2][2 * HDIM + h] * xq;
        acc3 += sw[3][h] * x0 + sw[3][HDIM + h] * x1 + sw[3][2 * HDIM + h] * xq;
    }
    red[0][warp][b] = acc0;
    red[1][warp][b] = acc1;
    red[2][warp][b] = acc2;
    red[3][warp][b] = acc3;
    __syncthreads();

    if (t < BDIM * OPB) {
        int o  = t >> 5;
        int b2 = t & 31;
        float s = 0.f;
        #pragma unroll
        for (int w = 0; w < 8; w++) s += red[o][w][b2];
        out[BDIM * NDIM + b2 * HDIM + (o0 + o)] = s;
    }
}

// ---------------------------------------------------------------------------
// Launch. Inputs: Q, K, V, adj, s_mask, w_att, b_att, Wr0, Wr1, Wri.
// Output: [attn (B*N) | attn_sum (B*H)] floats.
// ---------------------------------------------------------------------------
extern "C" void kernel_launch(void* const* d_in, const int* in_sizes, int n_in,
                              void* d_out, int out_size)
{
    const float* Q      = (const float*)d_in[0];
    const float* Kmat   = (const float*)d_in[1];
    const float* V      = (const float*)d_in[2];
    const int*   adj    = (const int*)  d_in[3];
    const int*   s_mask = (const int*)  d_in[4];
    const float* w_att  = (const float*)d_in[5];
    // d_in[6] = b_att (cancels in softmax)
    const float* Wr0    = (const float*)d_in[7];
    const float* Wr1    = (const float*)d_in[8];
    const float* Wri    = (const float*)d_in[9];
    float* out = (float*)d_out;

    k_alpha<<<(BDIM * NDIM) / 16, 256>>>(Kmat, w_att, adj);
    k_softmax<<<BDIM, 1024>>>(out, Q);
    dim3 g3(NCHUNK, BDIM);
    k_wsum<<<g3, 512>>>(V, s_mask, out);
    k_final<<<HDIM / OPB, 256>>>(Wr0, Wr1, Wri, out);
}

// round 12
// speedup vs baseline: 2.9848x; 1.1077x over previous
#include <cuda_runtime.h>

// Problem constants (fixed shapes)
#define BDIM 32
#define NDIM 2048
#define HDIM 512
#define NCHUNK 16
#define CHUNK (NDIM / NCHUNK)   // 128
#define MASK_NEG 1e30f
#define OPB 4                   // output columns per k_final block
#define HSPLIT 4                // h-segments for k_final
#define HSEG (HDIM / HSPLIT)    // 128

// Scratch (device globals: allowed; no runtime allocation)
__device__ float g_alpha[BDIM * NDIM];
__device__ float g_part0[BDIM * NCHUNK * HDIM];
__device__ float g_part1[BDIM * NCHUNK * HDIM];
__device__ float g_y0T[HDIM * BDIM];                 // [h][b]
__device__ float g_y1T[HDIM * BDIM];                 // [h][b]
__device__ float g_qT [HDIM * BDIM];                 // [h][b]
__device__ float g_fpart[HSPLIT][HDIM][BDIM];        // k_final partials
__device__ int   g_cnt[BDIM];                        // zero-init; self-reset
__device__ int   g_fcnt[HDIM / OPB];                 // zero-init; self-reset

// ---------------------------------------------------------------------------
// K1: alpha[b,n] = K[b,n,:] . wk - (1-adj)*1e30
// (Q.wq + b_att are per-row softmax constants -> skipped.)
// ---------------------------------------------------------------------------
__global__ __launch_bounds__(256)
void k_alpha(const float* __restrict__ Kmat,
             const float* __restrict__ w_att,
             const int*   __restrict__ adj)
{
    __shared__ float4 swk[HDIM / 4];
    int tid = threadIdx.x;
    if (tid < HDIM / 4)
        swk[tid] = ((const float4*)(w_att + HDIM))[tid];
    __syncthreads();

    int warp = tid >> 5, lane = tid & 31;
    int row0 = (blockIdx.x * 8 + warp) * 2;

    const float4* kp0 = (const float4*)(Kmat + (size_t)row0 * HDIM);
    const float4* kp1 = kp0 + HDIM / 4;

    float4 a[4], c[4];
    #pragma unroll
    for (int i = 0; i < 4; i++) a[i] = kp0[lane + i * 32];
    #pragma unroll
    for (int i = 0; i < 4; i++) c[i] = kp1[lane + i * 32];

    float acc0 = 0.f, acc1 = 0.f;
    #pragma unroll
    for (int i = 0; i < 4; i++) {
        float4 w4 = swk[lane + i * 32];
        acc0 += a[i].x * w4.x + a[i].y * w4.y + a[i].z * w4.z + a[i].w * w4.w;
        acc1 += c[i].x * w4.x + c[i].y * w4.y + c[i].z * w4.z + c[i].w * w4.w;
    }
    #pragma unroll
    for (int o = 16; o > 0; o >>= 1) {
        acc0 += __shfl_xor_sync(0xFFFFFFFFu, acc0, o);
        acc1 += __shfl_xor_sync(0xFFFFFFFFu, acc1, o);
    }

    if (lane == 0) {
        float m0 = (float)adj[row0];
        float m1 = (float)adj[row0 + 1];
        g_alpha[row0]     = acc0 - (1.0f - m0) * MASK_NEG;
        g_alpha[row0 + 1] = acc1 - (1.0f - m1) * MASK_NEG;
    }
}

// ---------------------------------------------------------------------------
// K2: row softmax over N=2048 (one block per b) -> d_out[0 .. B*N).
// Also transposes Q into g_qT.
// ---------------------------------------------------------------------------
__global__ __launch_bounds__(1024)
void k_softmax(float* __restrict__ out_attn,
               const float* __restrict__ Q)
{
    __shared__ float sred[32];
    __shared__ float s_bm, s_bs;
    int b   = blockIdx.x;
    int tid = threadIdx.x;
    const float* a = g_alpha + b * NDIM;

    if (tid < HDIM)
        g_qT[tid * BDIM + b] = Q[b * HDIM + tid];

    float v0 = a[tid], v1 = a[tid + 1024];

    float m = fmaxf(v0, v1);
    #pragma unroll
    for (int o = 16; o > 0; o >>= 1)
        m = fmaxf(m, __shfl_xor_sync(0xFFFFFFFFu, m, o));
    if ((tid & 31) == 0) sred[tid >> 5] = m;
    __syncthreads();
    if (tid < 32) {
        float t = sred[tid];
        #pragma unroll
        for (int o = 16; o > 0; o >>= 1)
            t = fmaxf(t, __shfl_xor_sync(0xFFFFFFFFu, t, o));
        if (tid == 0) s_bm = t;
    }
    __syncthreads();
    m = s_bm;

    float e0 = __expf(v0 - m), e1 = __expf(v1 - m);

    float s = e0 + e1;
    #pragma unroll
    for (int o = 16; o > 0; o >>= 1)
        s += __shfl_xor_sync(0xFFFFFFFFu, s, o);
    __syncthreads();
    if ((tid & 31) == 0) sred[tid >> 5] = s;
    __syncthreads();
    if (tid < 32) {
        float t = sred[tid];
        #pragma unroll
        for (int o = 16; o > 0; o >>= 1)
            t += __shfl_xor_sync(0xFFFFFFFFu, t, o);
        if (tid == 0) s_bs = t;
    }
    __syncthreads();
    float inv = 1.0f / s_bs;

    out_attn[b * NDIM + tid]        = e0 * inv;
    out_attn[b * NDIM + tid + 1024] = e1 * inv;
}

// ---------------------------------------------------------------------------
// K3: partial weighted V sums + fused last-block chunk reduce.
// ---------------------------------------------------------------------------
__global__ __launch_bounds__(512)
void k_wsum(const float* __restrict__ V,
            const int*   __restrict__ s_mask,
            const float* __restrict__ attn)
{
    __shared__ float  sw0[CHUNK];
    __shared__ float  sw1[CHUNK];
    __shared__ float4 red0[4][HDIM / 4];
    __shared__ float4 red1[4][HDIM / 4];
    __shared__ int    s_last;

    int c = blockIdx.x, b = blockIdx.y;
    int t  = threadIdx.x;
    int f4 = t & 127;
    int sg = t >> 7;
    int n0 = c * CHUNK;

    if (t < CHUNK) {
        float w   = attn[b * NDIM + n0 + t];
        float smf = (float)s_mask[b * NDIM + n0 + t];
        float ws  = w * smf;
        sw0[t] = ws;
        sw1[t] = w - ws;
    }
    __syncthreads();

    const float4* vp = (const float4*)(V + ((size_t)b * NDIM + n0 + sg * 32) * HDIM) + f4;
    const float* w0p = sw0 + sg * 32;
    const float* w1p = sw1 + sg * 32;

    float4 a0 = make_float4(0.f, 0.f, 0.f, 0.f);
    float4 a1 = make_float4(0.f, 0.f, 0.f, 0.f);
    #pragma unroll 8
    for (int n = 0; n < 32; n++) {
        float4 v = vp[n * (HDIM / 4)];
        float c0 = w0p[n], c1 = w1p[n];
        a0.x += c0 * v.x; a0.y += c0 * v.y; a0.z += c0 * v.z; a0.w += c0 * v.w;
        a1.x += c1 * v.x; a1.y += c1 * v.y; a1.z += c1 * v.z; a1.w += c1 * v.w;
    }
    red0[sg][f4] = a0;
    red1[sg][f4] = a1;
    __syncthreads();

    if (t < HDIM / 4) {
        float4 s0 = red0[0][t], s1 = red1[0][t];
        #pragma unroll
        for (int g = 1; g < 4; g++) {
            float4 p0 = red0[g][t], p1 = red1[g][t];
            s0.x += p0.x; s0.y += p0.y; s0.z += p0.z; s0.w += p0.w;
            s1.x += p1.x; s1.y += p1.y; s1.z += p1.z; s1.w += p1.w;
        }
        ((float4*)(g_part0 + (b * NCHUNK + c) * HDIM))[t] = s0;
        ((float4*)(g_part1 + (b * NCHUNK + c) * HDIM))[t] = s1;
    }

    __threadfence();
    __syncthreads();
    if (t == 0) {
        int v = atomicAdd(&g_cnt[b], 1);
        s_last = (v == NCHUNK - 1) ? 1 : 0;
    }
    __syncthreads();
    if (!s_last) return;
    __threadfence();

    int cg = t >> 7;
    {
        float4 s0 = make_float4(0.f, 0.f, 0.f, 0.f);
        float4 s1 = make_float4(0.f, 0.f, 0.f, 0.f);
        #pragma unroll
        for (int i = 0; i < 4; i++) {
            int cc = cg * 4 + i;
            float4 p0 = ((const float4*)(g_part0 + (b * NCHUNK + cc) * HDIM))[f4];
            float4 p1 = ((const float4*)(g_part1 + (b * NCHUNK + cc) * HDIM))[f4];
            s0.x += p0.x; s0.y += p0.y; s0.z += p0.z; s0.w += p0.w;
            s1.x += p1.x; s1.y += p1.y; s1.z += p1.z; s1.w += p1.w;
        }
        red0[cg][f4] = s0;
        red1[cg][f4] = s1;
    }
    __syncthreads();

    if (t < HDIM / 4) {
        float4 r0 = red0[0][t], r1 = red1[0][t];
        #pragma unroll
        for (int g = 1; g < 4; g++) {
            float4 p0 = red0[g][t], p1 = red1[g][t];
            r0.x += p0.x; r0.y += p0.y; r0.z += p0.z; r0.w += p0.w;
            r1.x += p1.x; r1.y += p1.y; r1.z += p1.z; r1.w += p1.w;
        }
        int h = t * 4;
        g_y0T[(h + 0) * BDIM + b] = r0.x;
        g_y0T[(h + 1) * BDIM + b] = r0.y;
        g_y0T[(h + 2) * BDIM + b] = r0.z;
        g_y0T[(h + 3) * BDIM + b] = r0.w;
        g_y1T[(h + 0) * BDIM + b] = r1.x;
        g_y1T[(h + 1) * BDIM + b] = r1.y;
        g_y1T[(h + 2) * BDIM + b] = r1.z;
        g_y1T[(h + 3) * BDIM + b] = r1.w;
    }
    if (t == 0) g_cnt[b] = 0;
}

// ---------------------------------------------------------------------------
// K4: attn_sum[b,o] = sum_h Wr0[o,h]*y0[b,h] + Wr1[o,h]*y1[b,h] + Wri[o,h]*Q[b,h]
// Grid (HDIM/OPB, HSPLIT) = (128, 4) = 512 blocks, 256 threads.
// Each block: OPB output columns x one 128-h segment. 48 independent LDGs
// per thread; deterministic warp+segment combines (counter pattern).
// ---------------------------------------------------------------------------
__global__ __launch_bounds__(256)
void k_final(const float* __restrict__ Wr0,
             const float* __restrict__ Wr1,
             const float* __restrict__ Wri,
             float* __restrict__ out)
{
    __shared__ float sw[OPB][3 * HSEG];     // per-o: [wr0seg | wr1seg | wriseg]
    __shared__ float red[OPB][8][BDIM];
    __shared__ int   s_last;

    int t     = threadIdx.x;
    int o0    = blockIdx.x * OPB;
    int hs    = blockIdx.y;
    int hbase = hs * HSEG;

    // Stage weight segments: OPB*3*HSEG/4 = 384 float4 over 256 threads
    for (int i = t; i < OPB * 3 * (HSEG / 4); i += 256) {
        int o     = i / (3 * (HSEG / 4));
        int r     = i % (3 * (HSEG / 4));
        int which = r / (HSEG / 4);
        int j     = r % (HSEG / 4);
        const float* src = (which == 0) ? Wr0 : (which == 1) ? Wr1 : Wri;
        ((float4*)sw[o])[r] =
            ((const float4*)(src + (size_t)(o0 + o) * HDIM + hbase))[j];
    }
    __syncthreads();

    int warp = t >> 5, b = t & 31;
    int h0 = warp * (HSEG / 8);             // 16 h per warp

    float acc0 = 0.f, acc1 = 0.f, acc2 = 0.f, acc3 = 0.f;
    #pragma unroll
    for (int i = 0; i < HSEG / 8; i++) {
        int hl = h0 + i;
        int h  = hbase + hl;
        float x0 = g_y0T[h * BDIM + b];
        float x1 = g_y1T[h * BDIM + b];
        float xq = g_qT [h * BDIM + b];
        acc0 += sw[0][hl] * x0 + sw[0][HSEG + hl] * x1 + sw[0][2 * HSEG + hl] * xq;
        acc1 += sw[1][hl] * x0 + sw[1][HSEG + hl] * x1 + sw[1][2 * HSEG + hl] * xq;
        acc2 += sw[2][hl] * x0 + sw[2][HSEG + hl] * x1 + sw[2][2 * HSEG + hl] * xq;
        acc3 += sw[3][hl] * x0 + sw[3][HSEG + hl] * x1 + sw[3][2 * HSEG + hl] * xq;
    }
    red[0][warp][b] = acc0;
    red[1][warp][b] = acc1;
    red[2][warp][b] = acc2;
    red[3][warp][b] = acc3;
    __syncthreads();

    // Combine 8 warps -> this segment's partial
    if (t < OPB * BDIM) {
        int o  = t >> 5;
        int b2 = t & 31;
        float s = 0.f;
        #pragma unroll
        for (int w = 0; w < 8; w++) s += red[o][w][b2];
        g_fpart[hs][o0 + o][b2] = s;
    }

    // Last segment-block per o-group combines the HSPLIT partials (fixed order)
    __threadfence();
    __syncthreads();
    if (t == 0) {
        int v = atomicAdd(&g_fcnt[blockIdx.x], 1);
        s_last = (v == HSPLIT - 1) ? 1 : 0;
    }
    __syncthreads();
    if (!s_last) return;
    __threadfence();

    if (t < OPB * BDIM) {
        int o  = t >> 5;
        int b2 = t & 31;
        float s = 0.f;
        #pragma unroll
        for (int k = 0; k < HSPLIT; k++) s += g_fpart[k][o0 + o][b2];
        out[BDIM * NDIM + b2 * HDIM + (o0 + o)] = s;
    }
    if (t == 0) g_fcnt[blockIdx.x] = 0;
}

// ---------------------------------------------------------------------------
// Launch. Inputs: Q, K, V, adj, s_mask, w_att, b_att, Wr0, Wr1, Wri.
// Output: [attn (B*N) | attn_sum (B*H)] floats.
// ---------------------------------------------------------------------------
extern "C" void kernel_launch(void* const* d_in, const int* in_sizes, int n_in,
                              void* d_out, int out_size)
{
    const float* Q      = (const float*)d_in[0];
    const float* Kmat   = (const float*)d_in[1];
    const float* V      = (const float*)d_in[2];
    const int*   adj    = (const int*)  d_in[3];
    const int*   s_mask = (const int*)  d_in[4];
    const float* w_att  = (const float*)d_in[5];
    // d_in[6] = b_att (cancels in softmax)
    const float* Wr0    = (const float*)d_in[7];
    const float* Wr1    = (const float*)d_in[8];
    const float* Wri    = (const float*)d_in[9];
    float* out = (float*)d_out;

    k_alpha<<<(BDIM * NDIM) / 16, 256>>>(Kmat, w_att, adj);
    k_softmax<<<BDIM, 1024>>>(out, Q);
    dim3 g3(NCHUNK, BDIM);
    k_wsum<<<g3, 512>>>(V, s_mask, out);
    dim3 g4(HDIM / OPB, HSPLIT);
    k_final<<<g4, 256>>>(Wr0, Wr1, Wri, out);
}